// round 10
// baseline (speedup 1.0000x reference)
#include <cuda_runtime.h>

#define T_TOT   512
#define NF      16
#define NCHUNK  128
#define XROW    20

using u64 = unsigned long long;

#define PACK2(d, lo, hi)   asm("mov.b64 %0, {%1, %2};" : "=l"(d) : "f"(lo), "f"(hi))
#define UNPACK2(lo, hi, s) asm("mov.b64 {%0, %1}, %2;" : "=f"(lo), "=f"(hi) : "l"(s))
#define FMA2(d, a, b, c)   asm("fma.rn.f32x2 %0, %1, %2, %3;" : "=l"(d) : "l"(a), "l"(b), "l"(c))

union Q4 { float4 f; u64 u[2]; };

__global__ void __launch_bounds__(256, 1)
gru_stagger_kernel(const float* __restrict__ x,
                   const float* __restrict__ w_ih,
                   const float* __restrict__ w_hh,
                   const float* __restrict__ b_ih,
                   const float* __restrict__ b_hh,
                   const float* __restrict__ fc_w,
                   const float* __restrict__ fc_b,
                   float* __restrict__ out)
{
    // per-warp double-buffered x tile: 16 rows (4 batches x 4 t) x XROW floats
    __shared__ __align__(16) float xs[8][2][16 * XROW];   // 20480 B

    const int tid   = threadIdx.x;
    const int wid   = tid >> 5;
    const int lane  = tid & 31;
    const int m     = lane & 3;
    const int cbp   = (lane >> 2) & 3;
    const int halfp = lane >> 4;
    const int batch0 = blockIdx.x * 32 + wid * 4;

    // ---- producer weights: gates {m, 4+m, 8+m} packed over feature pairs.
    //      r/z rows pre-halved; (b_ih+b_hh) folded for r/z, b_ih for n. ----
    u64 wp[3][8];
    float bs[3];
    #pragma unroll
    for (int q = 0; q < 3; ++q) {
        const int g = q * 4 + m;
        const float sc = (q < 2) ? 0.5f : 1.0f;
        const float* wr = w_ih + g * NF;
        #pragma unroll
        for (int k = 0; k < 8; ++k) PACK2(wp[q][k], wr[2 * k] * sc, wr[2 * k + 1] * sc);
        bs[q] = (q < 2) ? 0.5f * (b_ih[g] + b_hh[g]) : b_ih[g];
    }

    // ---- consumer weights (lanes 0-15): r/z pre-halved ----
    float whr[4], whz[4], whn[4];
    #pragma unroll
    for (int k = 0; k < 4; ++k) {
        whr[k] = 0.5f * w_hh[m * 4 + k];
        whz[k] = 0.5f * w_hh[(4 + m) * 4 + k];
        whn[k] = w_hh[(8 + m) * 4 + k];
    }
    const float bhn = b_hh[8 + m];
    const float fw0 = fc_w[0], fw1 = fc_w[1], fw2 = fc_w[2], fw3 = fc_w[3];
    const float fb  = fc_b[0];

    float h0 = 0.f, h1 = 0.f, h2 = 0.f, h3 = 0.f, hown = 0.f;
    const int src = lane & 12;

    // ---- warp-cooperative coalesced x load: 64 float4/chunk, 2 per lane ----
    const int b_0 = lane >> 4,        b_1 = 2 + (lane >> 4);
    const int t_l = (lane >> 2) & 3,  f_l = lane & 3;
    const float* p0 = x + ((size_t)(batch0 + b_0) * T_TOT + t_l) * NF + f_l * 4;
    const float* p1 = x + ((size_t)(batch0 + b_1) * T_TOT + t_l) * NF + f_l * 4;
    const int soff0 = (b_0 * 4 + t_l) * XROW + f_l * 4;
    const int soff1 = (b_1 * 4 + t_l) * XROW + f_l * 4;

    float4 xn0, xn1;
    auto ldx = [&](int tc) {
        xn0 = *(const float4*)(p0 + (size_t)tc * 64);
        xn1 = *(const float4*)(p1 + (size_t)tc * 64);
    };
    auto stx = [&](int buf) {
        float* w = xs[wid][buf];
        *(float4*)(w + soff0) = xn0;
        *(float4*)(w + soff1) = xn1;
    };

    // ---- produce: lane's t-half (2 timesteps) x 3 gate-dots (biases folded) ----
    auto produce = [&](int buf, float (&gl)[6]) {
        const float* base = xs[wid][buf] + (cbp * 4 + halfp * 2) * XROW;
        #pragma unroll
        for (int tt = 0; tt < 2; ++tt) {
            const float* r = base + tt * XROW;
            Q4 q0 = *(const Q4*)(r);
            Q4 q1 = *(const Q4*)(r + 4);
            Q4 q2 = *(const Q4*)(r + 8);
            Q4 q3 = *(const Q4*)(r + 12);
            #pragma unroll
            for (int q = 0; q < 3; ++q) {
                u64 acc; PACK2(acc, bs[q], 0.0f);
                FMA2(acc, q0.u[0], wp[q][0], acc);
                FMA2(acc, q0.u[1], wp[q][1], acc);
                FMA2(acc, q1.u[0], wp[q][2], acc);
                FMA2(acc, q1.u[1], wp[q][3], acc);
                FMA2(acc, q2.u[0], wp[q][4], acc);
                FMA2(acc, q2.u[1], wp[q][5], acc);
                FMA2(acc, q3.u[0], wp[q][6], acc);
                FMA2(acc, q3.u[1], wp[q][7], acc);
                float lo, hi; UNPACK2(lo, hi, acc);
                gl[tt * 3 + q] = lo + hi;
            }
        }
    };
    auto xchg = [&](const float (&gl)[6], float (&gu)[6]) {
        #pragma unroll
        for (int k = 0; k < 6; ++k)
            gu[k] = __shfl_sync(0xffffffffu, gl[k], lane | 16);
    };

    // ---- consume: 4 GRU steps (lanes 0-15; math = validated R6 + foldings) ----
    auto consume = [&](const float (&gl)[6], const float (&gu)[6]) {
        #pragma unroll
        for (int s = 0; s < 4; ++s) {
            const float gr = (s < 2) ? gl[s * 3 + 0] : gu[(s - 2) * 3 + 0]; // = (gi_r+b)/2
            const float gz = (s < 2) ? gl[s * 3 + 1] : gu[(s - 2) * 3 + 1]; // = (gi_z+b)/2
            const float gn = (s < 2) ? gl[s * 3 + 2] : gu[(s - 2) * 3 + 2]; // = gi_n+b_ih

            float yr = fmaf(whr[3], h3, fmaf(whr[2], h2,
                       fmaf(whr[1], h1, fmaf(whr[0], h0, gr))));   // a_r/2
            float yz = fmaf(whz[3], h3, fmaf(whz[2], h2,
                       fmaf(whz[1], h1, fmaf(whz[0], h0, gz))));   // a_z/2
            float ghn = fmaf(whn[3], h3, fmaf(whn[2], h2,
                        fmaf(whn[1], h1, fmaf(whn[0], h0, bhn))));

            // tanh(y) odd poly (|y|<=0.6, validated)
            float ur = yr * yr;
            float pr = fmaf(ur, fmaf(ur, -0.05396825f, 0.13333333f), -0.33333333f);
            float thr = fmaf(yr * ur, pr, yr);
            float uz = yz * yz;
            float pz = fmaf(uz, fmaf(uz, -0.05396825f, 0.13333333f), -0.33333333f);
            float zg = fmaf(fmaf(yz * uz, pz, yz), 0.5f, 0.5f);

            // na = gi_n + sigmoid(a_r)*gh_n = (gn + ghn/2) + thr*(ghn/2)
            float ghn2 = 0.5f * ghn;
            float basen = gn + ghn2;
            float na = fmaf(thr, ghn2, basen);

            // n = tanh(na), Pade[5,4] (validated)
            float un   = na * na;
            float nnum = fmaf(un, un + 105.f, 945.f);
            float nden = fmaf(un, fmaf(un, 15.f, 420.f), 945.f);
            float ng   = na * __fdividef(nnum, nden);

            float hm = fmaf(zg, hown - ng, ng);
            hown = hm;
            h0 = __shfl_sync(0x0000ffffu, hm, src | 0);
            h1 = __shfl_sync(0x0000ffffu, hm, src | 1);
            h2 = __shfl_sync(0x0000ffffu, hm, src | 2);
            h3 = __shfl_sync(0x0000ffffu, hm, src | 3);
        }
    };

    float glA[6], guA[6], glB[6], guB[6];

    // ---- prologue: tile(0) -> buf0, produce chunk0, x(1) in flight ----
    ldx(0);
    stx(0);
    __syncwarp();
    ldx(1);
    produce(0, glA);
    xchg(glA, guA);

    if (wid < 4) {
        // ============ variant P: produce-first (warps 0-3) ============
        #pragma unroll 1
        for (int it = 0; it < NCHUNK; it += 2) {
            stx(1);
            __syncwarp();
            ldx(min(it + 2, NCHUNK - 1));
            produce(1, glB);
            xchg(glB, guB);
            if (lane < 16) consume(glA, guA);

            stx(0);
            __syncwarp();
            ldx(min(it + 3, NCHUNK - 1));
            produce(0, glA);
            xchg(glA, guA);
            if (lane < 16) consume(glB, guB);
        }
    } else {
        // ============ variant C: consume-first (warps 4-7, same SMSPs) ============
        #pragma unroll 1
        for (int it = 0; it < NCHUNK; it += 2) {
            if (lane < 16) consume(glA, guA);
            stx(1);
            __syncwarp();
            ldx(min(it + 2, NCHUNK - 1));
            produce(1, glB);
            xchg(glB, guB);

            if (lane < 16) consume(glB, guB);
            stx(0);
            __syncwarp();
            ldx(min(it + 3, NCHUNK - 1));
            produce(0, glA);
            xchg(glA, guA);
        }
    }

    if (lane < 16 && m == 0) {
        out[batch0 + cbp] = fmaf(h3, fw3, fmaf(h2, fw2,
                            fmaf(h1, fw1, fmaf(h0, fw0, fb))));
    }
}

extern "C" void kernel_launch(void* const* d_in, const int* in_sizes, int n_in,
                              void* d_out, int out_size)
{
    const float* x    = (const float*)d_in[0];
    const float* w_ih = (const float*)d_in[1];
    const float* w_hh = (const float*)d_in[2];
    const float* b_ih = (const float*)d_in[3];
    const float* b_hh = (const float*)d_in[4];
    const float* fc_w = (const float*)d_in[5];
    const float* fc_b = (const float*)d_in[6];
    float* out = (float*)d_out;

    gru_stagger_kernel<<<4096 / 32, 256>>>(x, w_ih, w_hh, b_ih, b_hh, fc_w, fc_b, out);
}

// round 11
// speedup vs baseline: 1.6957x; 1.6957x over previous
#include <cuda_runtime.h>

#define T_TOT   512
#define NF      16
#define NCHUNK  128     // chunks of 4 timesteps
#define XROW    20      // 16 floats + 4 pad

using u64 = unsigned long long;

#define PACK2(d, lo, hi)   asm("mov.b64 %0, {%1, %2};" : "=l"(d) : "f"(lo), "f"(hi))
#define UNPACK2(lo, hi, s) asm("mov.b64 {%0, %1}, %2;" : "=f"(lo), "=f"(hi) : "l"(s))
#define FMA2(d, a, b, c)   asm("fma.rn.f32x2 %0, %1, %2, %3;" : "=l"(d) : "l"(a), "l"(b), "l"(c))

union Q4 { float4 f; u64 u[2]; };

__global__ void __launch_bounds__(256, 1)
gru_warp_kernel(const float* __restrict__ x,
                const float* __restrict__ w_ih,
                const float* __restrict__ w_hh,
                const float* __restrict__ b_ih,
                const float* __restrict__ b_hh,
                const float* __restrict__ fc_w,
                const float* __restrict__ fc_b,
                float* __restrict__ out)
{
    // per-warp double-buffered x tile: 16 rows (4 batches x 4 t) x XROW floats
    __shared__ __align__(16) float xs[8][2][16 * XROW];   // 20480 B

    const int tid   = threadIdx.x;
    const int wid   = tid >> 5;
    const int lane  = tid & 31;
    const int m     = lane & 3;            // gate-unit / feature-quad slot
    const int cbp   = (lane >> 2) & 3;     // batch within warp (0..3)
    const int halfp = lane >> 4;           // produce t-half
    const int batch0 = blockIdx.x * 32 + wid * 4;

    // ===== ANTI-PHASE STAGGER: desync SMSP partner warps by ~400 cyc =====
    // wid 0-3 and wid 4-7 pair up on SMSP (wid & 3). A one-time dependent
    // FMA chain on wid>=4 offsets the two identical instruction streams so
    // one warp's produce/issue phase covers the other's serial consume chain.
    if (wid >= 4) {
        float d = 1.0f;
        #pragma unroll
        for (int i = 0; i < 100; ++i)
            asm volatile("fma.rn.f32 %0, %0, %1, %2;"
                         : "+f"(d) : "f"(1.0000001f), "f"(1e-30f));
        if (d == 2.0f) out[batch0] = d;    // never true; defeats DCE
    }

    // ---- producer weights: gates {m, 4+m, 8+m}, packed over feature pairs ----
    u64 wp[3][8];
    u64 bq[3];
    #pragma unroll
    for (int q = 0; q < 3; ++q) {
        const int g = q * 4 + m;
        const float* wr = w_ih + g * NF;
        #pragma unroll
        for (int k = 0; k < 8; ++k) PACK2(wp[q][k], wr[2 * k], wr[2 * k + 1]);
        PACK2(bq[q], b_ih[g], 0.0f);
    }

    // ---- consumer weights (lanes 0-15 use them) ----
    float whr[4], whz[4], whn[4];
    #pragma unroll
    for (int k = 0; k < 4; ++k) {
        whr[k] = w_hh[m * 4 + k];
        whz[k] = w_hh[(4 + m) * 4 + k];
        whn[k] = w_hh[(8 + m) * 4 + k];
    }
    const float bhr = b_hh[m], bhz = b_hh[4 + m], bhn = b_hh[8 + m];
    const float fw0 = fc_w[0], fw1 = fc_w[1], fw2 = fc_w[2], fw3 = fc_w[3];
    const float fb  = fc_b[0];

    float h0 = 0.f, h1 = 0.f, h2 = 0.f, h3 = 0.f, hown = 0.f;
    const int src = lane & 12;             // quad base within lanes 0..15

    // ---- warp-cooperative coalesced x load: 64 float4 per chunk, 2 per lane ----
    const int b_0 = lane >> 4,        b_1 = 2 + (lane >> 4);
    const int t_l = (lane >> 2) & 3,  f_l = lane & 3;
    const float* p0 = x + ((size_t)(batch0 + b_0) * T_TOT + t_l) * NF + f_l * 4;
    const float* p1 = x + ((size_t)(batch0 + b_1) * T_TOT + t_l) * NF + f_l * 4;
    const int soff0 = (b_0 * 4 + t_l) * XROW + f_l * 4;
    const int soff1 = (b_1 * 4 + t_l) * XROW + f_l * 4;

    float4 xn0, xn1;
    auto ldx = [&](int tc) {
        xn0 = *(const float4*)(p0 + (size_t)tc * 64);
        xn1 = *(const float4*)(p1 + (size_t)tc * 64);
    };
    auto stx = [&](int buf) {
        float* w = xs[wid][buf];
        *(float4*)(w + soff0) = xn0;
        *(float4*)(w + soff1) = xn1;
    };

    // ---- produce: this lane's t-half (2 timesteps) x 3 gate-dots ----
    auto produce = [&](int buf, float (&gl)[6]) {
        const float* base = xs[wid][buf] + (cbp * 4 + halfp * 2) * XROW;
        #pragma unroll
        for (int tt = 0; tt < 2; ++tt) {
            const float* r = base + tt * XROW;
            Q4 q0 = *(const Q4*)(r);
            Q4 q1 = *(const Q4*)(r + 4);
            Q4 q2 = *(const Q4*)(r + 8);
            Q4 q3 = *(const Q4*)(r + 12);
            #pragma unroll
            for (int q = 0; q < 3; ++q) {
                u64 acc = bq[q];
                FMA2(acc, q0.u[0], wp[q][0], acc);
                FMA2(acc, q0.u[1], wp[q][1], acc);
                FMA2(acc, q1.u[0], wp[q][2], acc);
                FMA2(acc, q1.u[1], wp[q][3], acc);
                FMA2(acc, q2.u[0], wp[q][4], acc);
                FMA2(acc, q2.u[1], wp[q][5], acc);
                FMA2(acc, q3.u[0], wp[q][6], acc);
                FMA2(acc, q3.u[1], wp[q][7], acc);
                float lo, hi; UNPACK2(lo, hi, acc);
                gl[tt * 3 + q] = lo + hi;
            }
        }
    };
    auto xchg = [&](const float (&gl)[6], float (&gu)[6]) {
        #pragma unroll
        for (int k = 0; k < 6; ++k)
            gu[k] = __shfl_sync(0xffffffffu, gl[k], lane | 16);
    };

    // ---- consume: 4 GRU steps (lanes 0-15 only; math validated R5/R6) ----
    auto consume = [&](const float (&gl)[6], const float (&gu)[6]) {
        #pragma unroll
        for (int s = 0; s < 4; ++s) {
            const float gir = (s < 2) ? gl[s * 3 + 0] : gu[(s - 2) * 3 + 0];
            const float giz = (s < 2) ? gl[s * 3 + 1] : gu[(s - 2) * 3 + 1];
            const float gin = (s < 2) ? gl[s * 3 + 2] : gu[(s - 2) * 3 + 2];

            float ghr = fmaf(whr[3], h3, fmaf(whr[2], h2,
                        fmaf(whr[1], h1, fmaf(whr[0], h0, bhr))));
            float ghz = fmaf(whz[3], h3, fmaf(whz[2], h2,
                        fmaf(whz[1], h1, fmaf(whz[0], h0, bhz))));
            float ghn = fmaf(whn[3], h3, fmaf(whn[2], h2,
                        fmaf(whn[1], h1, fmaf(whn[0], h0, bhn))));
            float ar = gir + ghr;
            float az = giz + ghz;

            // sigmoid(a) = 0.5 + 0.5*tanh(a/2); tanh via odd poly (|a/2| <= 0.6)
            float yr = 0.5f * ar, urr = yr * yr;
            float pr = fmaf(urr, fmaf(urr, -0.05396825f, 0.13333333f), -0.33333333f);
            float rg = fmaf(fmaf(yr * urr, pr, yr), 0.5f, 0.5f);

            float yz = 0.5f * az, uzz = yz * yz;
            float pz = fmaf(uzz, fmaf(uzz, -0.05396825f, 0.13333333f), -0.33333333f);
            float zg = fmaf(fmaf(yz * uzz, pz, yz), 0.5f, 0.5f);

            // n = tanh(gi_n + r*gh_n), Pade[5,4]
            float na   = fmaf(rg, ghn, gin);
            float un   = na * na;
            float nnum = fmaf(un, un + 105.f, 945.f);
            float nden = fmaf(un, fmaf(un, 15.f, 420.f), 945.f);
            float ng   = na * __fdividef(nnum, nden);

            float hm = fmaf(zg, hown - ng, ng);
            hown = hm;
            h0 = __shfl_sync(0x0000ffffu, hm, src | 0);
            h1 = __shfl_sync(0x0000ffffu, hm, src | 1);
            h2 = __shfl_sync(0x0000ffffu, hm, src | 2);
            h3 = __shfl_sync(0x0000ffffu, hm, src | 3);
        }
    };

    float glA[6], guA[6], glB[6], guB[6];

    // ---- prologue: tile(0) -> buf0, produce chunk0, x(1) in flight ----
    ldx(0);
    stx(0);
    __syncwarp();
    ldx(1);
    produce(0, glA);
    xchg(glA, guA);

    #pragma unroll 1
    for (int it = 0; it < NCHUNK; it += 2) {
        // half A: stage x(it+1)->buf1, produce(it+1)->B, consume(it)=A
        stx(1);
        __syncwarp();
        ldx(min(it + 2, NCHUNK - 1));
        produce(1, glB);
        xchg(glB, guB);
        if (lane < 16) consume(glA, guA);

        // half B: stage x(it+2)->buf0, produce(it+2)->A, consume(it+1)=B
        stx(0);
        __syncwarp();
        ldx(min(it + 3, NCHUNK - 1));
        produce(0, glA);
        xchg(glA, guA);
        if (lane < 16) consume(glB, guB);
    }

    if (lane < 16 && m == 0) {
        out[batch0 + cbp] = fmaf(h3, fw3, fmaf(h2, fw2,
                            fmaf(h1, fw1, fmaf(h0, fw0, fb))));
    }
}

extern "C" void kernel_launch(void* const* d_in, const int* in_sizes, int n_in,
                              void* d_out, int out_size)
{
    const float* x    = (const float*)d_in[0];
    const float* w_ih = (const float*)d_in[1];
    const float* w_hh = (const float*)d_in[2];
    const float* b_ih = (const float*)d_in[3];
    const float* b_hh = (const float*)d_in[4];
    const float* fc_w = (const float*)d_in[5];
    const float* fc_b = (const float*)d_in[6];
    float* out = (float*)d_out;

    gru_warp_kernel<<<4096 / 32, 256>>>(x, w_ih, w_hh, b_ih, b_hh, fc_w, fc_b, out);
}

// round 12
// speedup vs baseline: 2.0555x; 1.2122x over previous
#include <cuda_runtime.h>
#include <cstdint>

#define T_TOT   512
#define NF      16
#define NCHUNK  128     // chunks of 4 timesteps
#define XROW    20      // 16 floats + 4 pad per (b,t) row
#define TILE_F  (16 * XROW)          // floats per ring buffer
#define TILE_B  (TILE_F * 4)         // bytes per ring buffer

using u64 = unsigned long long;

#define PACK2(d, lo, hi)   asm("mov.b64 %0, {%1, %2};" : "=l"(d) : "f"(lo), "f"(hi))
#define UNPACK2(lo, hi, s) asm("mov.b64 {%0, %1}, %2;" : "=f"(lo), "=f"(hi) : "l"(s))
#define FMA2(d, a, b, c)   asm("fma.rn.f32x2 %0, %1, %2, %3;" : "=l"(d) : "l"(a), "l"(b), "l"(c))

#define CP_COMMIT() asm volatile("cp.async.commit_group;" ::: "memory")
#define CP_WAIT2()  asm volatile("cp.async.wait_group 2;" ::: "memory")

__device__ __forceinline__ void cp16(uint32_t smem_dst, const float* gsrc) {
    asm volatile("cp.async.ca.shared.global [%0], [%1], 16;"
                 :: "r"(smem_dst), "l"(gsrc) : "memory");
}

union Q4 { float4 f; u64 u[2]; };

__global__ void __launch_bounds__(256, 1)
gru_cpasync_kernel(const float* __restrict__ x,
                   const float* __restrict__ w_ih,
                   const float* __restrict__ w_hh,
                   const float* __restrict__ b_ih,
                   const float* __restrict__ b_hh,
                   const float* __restrict__ fc_w,
                   const float* __restrict__ fc_b,
                   float* __restrict__ out)
{
    // per-warp 4-deep x ring: 4 bufs x 16 rows x XROW floats
    __shared__ __align__(16) float xs[8][4][TILE_F];    // 40960 B

    const int tid   = threadIdx.x;
    const int wid   = tid >> 5;
    const int lane  = tid & 31;
    const int m     = lane & 3;            // gate-unit / feature-quad slot
    const int cbp   = (lane >> 2) & 3;     // batch within warp (0..3)
    const int halfp = lane >> 4;           // produce t-half
    const int batch0 = blockIdx.x * 32 + wid * 4;

    // ---- producer weights: gates {m, 4+m, 8+m}, packed over feature pairs ----
    u64 wp[3][8];
    u64 bq[3];
    #pragma unroll
    for (int q = 0; q < 3; ++q) {
        const int g = q * 4 + m;
        const float* wr = w_ih + g * NF;
        #pragma unroll
        for (int k = 0; k < 8; ++k) PACK2(wp[q][k], wr[2 * k], wr[2 * k + 1]);
        PACK2(bq[q], b_ih[g], 0.0f);
    }

    // ---- consumer weights ----
    float whr[4], whz[4], whn[4];
    #pragma unroll
    for (int k = 0; k < 4; ++k) {
        whr[k] = w_hh[m * 4 + k];
        whz[k] = w_hh[(4 + m) * 4 + k];
        whn[k] = w_hh[(8 + m) * 4 + k];
    }
    const float bhr = b_hh[m], bhz = b_hh[4 + m], bhn = b_hh[8 + m];
    const float fw0 = fc_w[0], fw1 = fc_w[1], fw2 = fc_w[2], fw3 = fc_w[3];
    const float fb  = fc_b[0];

    float h0 = 0.f, h1 = 0.f, h2 = 0.f, h3 = 0.f, hown = 0.f;
    const int src = lane & 12;             // quad base within lower half

    // ---- async x staging: 64 float4 per warp-chunk, 2 per lane ----
    const int b_0 = lane >> 4,        b_1 = 2 + (lane >> 4);
    const int t_l = (lane >> 2) & 3,  f_l = lane & 3;
    const float* p0 = x + ((size_t)(batch0 + b_0) * T_TOT + t_l) * NF + f_l * 4;
    const float* p1 = x + ((size_t)(batch0 + b_1) * T_TOT + t_l) * NF + f_l * 4;
    const uint32_t sbase = (uint32_t)__cvta_generic_to_shared(&xs[wid][0][0]);
    const uint32_t d0 = sbase + ((b_0 * 4 + t_l) * XROW + f_l * 4) * 4;
    const uint32_t d1 = sbase + ((b_1 * 4 + t_l) * XROW + f_l * 4) * 4;

    auto issue = [&](int c) {
        if (c < NCHUNK) {
            const uint32_t boff = (uint32_t)(c & 3) * TILE_B;
            cp16(d0 + boff, p0 + (size_t)c * 64);
            cp16(d1 + boff, p1 + (size_t)c * 64);
        }
        CP_COMMIT();                         // empty groups keep the count aligned
    };

    // ---- produce: this lane's t-half (2 timesteps) x 3 gate-dots ----
    auto produce = [&](int c, float (&gl)[6]) {
        const float* base = xs[wid][c & 3] + (cbp * 4 + halfp * 2) * XROW;
        #pragma unroll
        for (int tt = 0; tt < 2; ++tt) {
            const float* r = base + tt * XROW;
            Q4 q0 = *(const Q4*)(r);
            Q4 q1 = *(const Q4*)(r + 4);
            Q4 q2 = *(const Q4*)(r + 8);
            Q4 q3 = *(const Q4*)(r + 12);
            #pragma unroll
            for (int q = 0; q < 3; ++q) {
                u64 acc = bq[q];
                FMA2(acc, q0.u[0], wp[q][0], acc);
                FMA2(acc, q0.u[1], wp[q][1], acc);
                FMA2(acc, q1.u[0], wp[q][2], acc);
                FMA2(acc, q1.u[1], wp[q][3], acc);
                FMA2(acc, q2.u[0], wp[q][4], acc);
                FMA2(acc, q2.u[1], wp[q][5], acc);
                FMA2(acc, q3.u[0], wp[q][6], acc);
                FMA2(acc, q3.u[1], wp[q][7], acc);
                float lo, hi; UNPACK2(lo, hi, acc);
                gl[tt * 3 + q] = lo + hi;
            }
        }
    };
    auto xchg = [&](const float (&gl)[6], float (&gu)[6]) {
        #pragma unroll
        for (int k = 0; k < 6; ++k)
            gu[k] = __shfl_sync(0xffffffffu, gl[k], lane | 16);
    };

    // ---- consume: 4 GRU steps; ALL lanes run it (uppers: bounded don't-cares) ----
    auto consume = [&](const float (&gl)[6], const float (&gu)[6]) {
        #pragma unroll
        for (int s = 0; s < 4; ++s) {
            const float gir = (s < 2) ? gl[s * 3 + 0] : gu[(s - 2) * 3 + 0];
            const float giz = (s < 2) ? gl[s * 3 + 1] : gu[(s - 2) * 3 + 1];
            const float gin = (s < 2) ? gl[s * 3 + 2] : gu[(s - 2) * 3 + 2];

            float ghr = fmaf(whr[3], h3, fmaf(whr[2], h2,
                        fmaf(whr[1], h1, fmaf(whr[0], h0, bhr))));
            float ghz = fmaf(whz[3], h3, fmaf(whz[2], h2,
                        fmaf(whz[1], h1, fmaf(whz[0], h0, bhz))));
            float ghn = fmaf(whn[3], h3, fmaf(whn[2], h2,
                        fmaf(whn[1], h1, fmaf(whn[0], h0, bhn))));
            float ar = gir + ghr;
            float az = giz + ghz;

            // sigmoid(a) = 0.5 + 0.5*tanh(a/2); tanh via odd poly (validated)
            float yr = 0.5f * ar, urr = yr * yr;
            float pr = fmaf(urr, fmaf(urr, -0.05396825f, 0.13333333f), -0.33333333f);
            float rg = fmaf(fmaf(yr * urr, pr, yr), 0.5f, 0.5f);

            float yz = 0.5f * az, uzz = yz * yz;
            float pz = fmaf(uzz, fmaf(uzz, -0.05396825f, 0.13333333f), -0.33333333f);
            float zg = fmaf(fmaf(yz * uzz, pz, yz), 0.5f, 0.5f);

            // n = tanh(gi_n + r*gh_n), Pade[5,4] (validated)
            float na   = fmaf(rg, ghn, gin);
            float un   = na * na;
            float nnum = fmaf(un, un + 105.f, 945.f);
            float nden = fmaf(un, fmaf(un, 15.f, 420.f), 945.f);
            float ng   = na * __fdividef(nnum, nden);

            float hm = fmaf(zg, hown - ng, ng);
            hown = hm;
            h0 = __shfl_sync(0xffffffffu, hm, src | 0);
            h1 = __shfl_sync(0xffffffffu, hm, src | 1);
            h2 = __shfl_sync(0xffffffffu, hm, src | 2);
            h3 = __shfl_sync(0xffffffffu, hm, src | 3);
        }
    };

    float glA[6], guA[6], glB[6], guB[6];

    // ---- prologue: fill the ring 3 deep, produce chunk 0 ----
    issue(0);
    issue(1);
    issue(2);
    CP_WAIT2();            // chunk 0 landed
    __syncwarp();
    produce(0, glA);
    xchg(glA, guA);

    #pragma unroll 1
    for (int it = 0; it < NCHUNK; it += 2) {
        // chunk it: prefetch it+3, produce it+1, consume it
        issue(it + 3);
        CP_WAIT2();                          // chunk it+1 landed
        __syncwarp();
        produce(it + 1, glB);                // (reads stale buf on last iter; unused)
        xchg(glB, guB);
        consume(glA, guA);

        // chunk it+1: prefetch it+4, produce it+2, consume it+1
        issue(it + 4);
        CP_WAIT2();                          // chunk it+2 landed
        __syncwarp();
        produce(it + 2, glA);
        xchg(glA, guA);
        consume(glB, guB);
    }

    if (lane < 16 && m == 0) {
        out[batch0 + cbp] = fmaf(h3, fw3, fmaf(h2, fw2,
                            fmaf(h1, fw1, fmaf(h0, fw0, fb))));
    }
}

extern "C" void kernel_launch(void* const* d_in, const int* in_sizes, int n_in,
                              void* d_out, int out_size)
{
    const float* x    = (const float*)d_in[0];
    const float* w_ih = (const float*)d_in[1];
    const float* w_hh = (const float*)d_in[2];
    const float* b_ih = (const float*)d_in[3];
    const float* b_hh = (const float*)d_in[4];
    const float* fc_w = (const float*)d_in[5];
    const float* fc_b = (const float*)d_in[6];
    float* out = (float*)d_out;

    gru_cpasync_kernel<<<4096 / 32, 256>>>(x, w_ih, w_hh, b_ih, b_hh, fc_w, fc_b, out);
}